// round 1
// baseline (speedup 1.0000x reference)
#include <cuda_runtime.h>
#include <math.h>

// Problem constants
#define B_   64
#define S_   4096
#define ENC_ 512
#define DEC_ 512

#define NCHUNK 8                  // S chunks per batch
#define CHUNK  (S_ / NCHUNK)      // 512 rows per chunk
#define NCTOT  (B_ * NCHUNK)      // 512 total chunks

// ---- scratch (no allocations allowed; __device__ globals) ----
__device__ float g_sub[B_ * ENC_];          // dec @ W^T            (128 KB)
__device__ float g_logits[B_ * S_];         // raw attention logits (1 MB)
__device__ float g_pm[NCTOT];               // per-chunk running max
__device__ float g_pl[NCTOT];               // per-chunk running denom
__device__ float g_pacc[NCTOT * ENC_];      // per-chunk weighted-sum vec (1 MB)

// ============================================================
// Kernel 1: sub[b,e] = sum_d dec[b,d] * W[e,d]     (tiny GEMV)
// grid = B_, block = 256 (8 warps); warp computes one e at a time
// ============================================================
__global__ __launch_bounds__(256) void sub_kernel(const float* __restrict__ dec,
                                                  const float* __restrict__ W) {
    const int b    = blockIdx.x;
    const int tid  = threadIdx.x;
    const int w    = tid >> 5;
    const int lane = tid & 31;

    __shared__ float dsm[DEC_];
    for (int i = tid; i < DEC_; i += 256) dsm[i] = dec[b * DEC_ + i];
    __syncthreads();

    const float4* d4 = (const float4*)dsm;

    for (int e = w; e < ENC_; e += 8) {
        const float4* Wr = (const float4*)(W + (size_t)e * DEC_);
        float s = 0.f;
#pragma unroll
        for (int j = 0; j < 4; j++) {
            float4 wv = Wr[lane + 32 * j];
            float4 dv = d4[lane + 32 * j];
            s += wv.x * dv.x + wv.y * dv.y + wv.z * dv.z + wv.w * dv.w;
        }
#pragma unroll
        for (int o = 16; o > 0; o >>= 1) s += __shfl_xor_sync(0xffffffffu, s, o);
        if (lane == 0) g_sub[b * ENC_ + e] = s;
    }
}

// ============================================================
// Kernel 2: streaming pass over encoder — logits + online softmax
// grid = (NCHUNK, B_), block = 256 (8 warps, warp-per-row)
// Each warp keeps (m, l, acc[512 distributed 16/lane]); merged per block.
// ============================================================
__global__ __launch_bounds__(256) void attn_pass1(const float* __restrict__ enc) {
    const int c    = blockIdx.x;          // chunk index within batch
    const int b    = blockIdx.y;
    const int tid  = threadIdx.x;
    const int w    = tid >> 5;
    const int lane = tid & 31;

    __shared__ float subsm[ENC_];
    __shared__ float accsm[8][ENC_];      // 16 KB
    __shared__ float msm[8], lsm[8];

    for (int i = tid; i < ENC_; i += 256) subsm[i] = g_sub[b * ENC_ + i];
    __syncthreads();

    // cache this lane's 16-float slice of sub in registers
    float4 subr[4];
    const float4* sub4 = (const float4*)subsm;
#pragma unroll
    for (int j = 0; j < 4; j++) subr[j] = sub4[lane + 32 * j];

    float m = -1e30f;
    float l = 0.f;
    float4 acc[4];
#pragma unroll
    for (int j = 0; j < 4; j++) acc[j] = make_float4(0.f, 0.f, 0.f, 0.f);

    const int s0 = c * CHUNK;
    const float* encb = enc + (size_t)b * S_ * ENC_;

    for (int r = w; r < CHUNK; r += 8) {
        const int s = s0 + r;
        const float4* er = (const float4*)(encb + (size_t)s * ENC_);

        float4 ev[4];
#pragma unroll
        for (int j = 0; j < 4; j++) ev[j] = er[lane + 32 * j];   // 4 indep loads (MLP=4)

        float dot = 0.f;
#pragma unroll
        for (int j = 0; j < 4; j++) {
            dot += ev[j].x * subr[j].x + ev[j].y * subr[j].y +
                   ev[j].z * subr[j].z + ev[j].w * subr[j].w;
        }
#pragma unroll
        for (int o = 16; o > 0; o >>= 1) dot += __shfl_xor_sync(0xffffffffu, dot, o);

        if (lane == 0) g_logits[b * S_ + s] = dot;

        // online softmax update (warp-uniform)
        const float mn    = fmaxf(m, dot);
        const float scale = __expf(m - mn);
        const float p     = __expf(dot - mn);
        l = l * scale + p;
#pragma unroll
        for (int j = 0; j < 4; j++) {
            acc[j].x = acc[j].x * scale + p * ev[j].x;
            acc[j].y = acc[j].y * scale + p * ev[j].y;
            acc[j].z = acc[j].z * scale + p * ev[j].z;
            acc[j].w = acc[j].w * scale + p * ev[j].w;
        }
        m = mn;
    }

    // spill warp state to smem
    float4* arow = (float4*)accsm[w];
#pragma unroll
    for (int j = 0; j < 4; j++) arow[lane + 32 * j] = acc[j];
    if (lane == 0) { msm[w] = m; lsm[w] = l; }
    __syncthreads();

    // block merge (every thread redundantly computes M,L — cheap)
    float M = -1e30f;
#pragma unroll
    for (int ww = 0; ww < 8; ww++) M = fmaxf(M, msm[ww]);
    float L = 0.f;
    float wts[8];
#pragma unroll
    for (int ww = 0; ww < 8; ww++) {
        wts[ww] = __expf(msm[ww] - M);
        L += lsm[ww] * wts[ww];
    }

    const int cid = b * NCHUNK + c;
    if (tid == 0) { g_pm[cid] = M; g_pl[cid] = L; }

    for (int e = tid; e < ENC_; e += 256) {
        float a = 0.f;
#pragma unroll
        for (int ww = 0; ww < 8; ww++) a += accsm[ww][e] * wts[ww];
        g_pacc[(size_t)cid * ENC_ + e] = a;
    }
}

// ============================================================
// Kernel 3: finalize — merge chunk partials, write attn + sumResult
// grid = B_, block = 256
// d_out layout: attn [B,1,S] then sumResult [B,ENC]
// ============================================================
__global__ __launch_bounds__(256) void finalize(float* __restrict__ out) {
    const int b   = blockIdx.x;
    const int tid = threadIdx.x;

    // global max/denom across chunks (redundant per thread; 8 loads each)
    float M = -1e30f;
#pragma unroll
    for (int c = 0; c < NCHUNK; c++) M = fmaxf(M, g_pm[b * NCHUNK + c]);
    float L = 0.f;
    float wts[NCHUNK];
#pragma unroll
    for (int c = 0; c < NCHUNK; c++) {
        wts[c] = __expf(g_pm[b * NCHUNK + c] - M);
        L += g_pl[b * NCHUNK + c] * wts[c];
    }
    const float invL = 1.f / L;

    // attn probabilities from stored logits
    const float* lg = g_logits + b * S_;
    float* attn_out = out + (size_t)b * S_;
    for (int s = tid; s < S_; s += 256)
        attn_out[s] = __expf(lg[s] - M) * invL;

    // sumResult
    float* sum_out = out + (size_t)B_ * S_ + (size_t)b * ENC_;
    for (int e = tid; e < ENC_; e += 256) {
        float a = 0.f;
#pragma unroll
        for (int c = 0; c < NCHUNK; c++)
            a += g_pacc[(size_t)(b * NCHUNK + c) * ENC_ + e] * wts[c];
        sum_out[e] = a * invL;
    }
}

// ============================================================
extern "C" void kernel_launch(void* const* d_in, const int* in_sizes, int n_in,
                              void* d_out, int out_size) {
    const float* dec = (const float*)d_in[0];  // [64,1,512]
    const float* enc = (const float*)d_in[1];  // [64,4096,512]
    const float* W   = (const float*)d_in[2];  // [512,512]
    float* out = (float*)d_out;

    sub_kernel<<<B_, 256>>>(dec, W);
    attn_pass1<<<dim3(NCHUNK, B_), 256>>>(enc);
    finalize<<<B_, 256>>>(out);
}

// round 2
// speedup vs baseline: 1.3657x; 1.3657x over previous
#include <cuda_runtime.h>
#include <math.h>

// Problem constants
#define B_   64
#define S_   4096
#define ENC_ 512
#define DEC_ 512

#define NCHUNK 8                  // S chunks per batch
#define CHUNK  (S_ / NCHUNK)      // 512 rows per chunk
#define NCTOT  (B_ * NCHUNK)      // 512 total chunks

// ---- scratch (no allocations allowed; __device__ globals) ----
__device__ float g_sub[B_ * ENC_];          // dec @ W^T            (128 KB)
__device__ float g_logits[B_ * S_];         // raw attention logits (1 MB)
__device__ float g_pm[NCTOT];               // per-chunk running max
__device__ float g_pl[NCTOT];               // per-chunk running denom
__device__ float g_pacc[NCTOT * ENC_];      // per-chunk weighted-sum vec (1 MB)

// ============================================================
// Kernel 1: sub[b,e] = sum_d dec[b,d] * W[e,d]     (tiny GEMV)
// grid = (ENC_/64, B_) = (8, 64) = 512 CTAs, block = 256 (8 warps)
// Each warp computes 8 e-values (vs 64 before) -> 8x more parallelism.
// ============================================================
__global__ __launch_bounds__(256) void sub_kernel(const float* __restrict__ dec,
                                                  const float* __restrict__ W) {
    const int et   = blockIdx.x;          // e-tile of 64
    const int b    = blockIdx.y;
    const int tid  = threadIdx.x;
    const int w    = tid >> 5;
    const int lane = tid & 31;

    __shared__ float dsm[DEC_];
    for (int i = tid; i < DEC_; i += 256) dsm[i] = dec[b * DEC_ + i];
    __syncthreads();

    const float4* d4 = (const float4*)dsm;

    // this lane's 16-float slice of dec in registers
    float4 dv[4];
#pragma unroll
    for (int j = 0; j < 4; j++) dv[j] = d4[lane + 32 * j];

    const int e0 = et * 64 + w * 8;       // warp handles e0 .. e0+7
#pragma unroll
    for (int i = 0; i < 8; i++) {
        const int e = e0 + i;
        const float4* Wr = (const float4*)(W + (size_t)e * DEC_);
        float s = 0.f;
#pragma unroll
        for (int j = 0; j < 4; j++) {
            float4 wv = Wr[lane + 32 * j];
            s += wv.x * dv[j].x + wv.y * dv[j].y + wv.z * dv[j].z + wv.w * dv[j].w;
        }
#pragma unroll
        for (int o = 16; o > 0; o >>= 1) s += __shfl_xor_sync(0xffffffffu, s, o);
        if (lane == 0) g_sub[b * ENC_ + e] = s;
    }
}

// ============================================================
// Kernel 2: streaming pass over encoder — logits + online softmax
// grid = (NCHUNK, B_), block = 256 (8 warps, warp-per-row)
// Each warp keeps (m, l, acc[512 distributed 16/lane]); merged per block.
// ============================================================
__global__ __launch_bounds__(256) void attn_pass1(const float* __restrict__ enc) {
    const int c    = blockIdx.x;          // chunk index within batch
    const int b    = blockIdx.y;
    const int tid  = threadIdx.x;
    const int w    = tid >> 5;
    const int lane = tid & 31;

    __shared__ float subsm[ENC_];
    __shared__ float accsm[8][ENC_];      // 16 KB
    __shared__ float msm[8], lsm[8];

    for (int i = tid; i < ENC_; i += 256) subsm[i] = g_sub[b * ENC_ + i];
    __syncthreads();

    // cache this lane's 16-float slice of sub in registers
    float4 subr[4];
    const float4* sub4 = (const float4*)subsm;
#pragma unroll
    for (int j = 0; j < 4; j++) subr[j] = sub4[lane + 32 * j];

    float m = -1e30f;
    float l = 0.f;
    float4 acc[4];
#pragma unroll
    for (int j = 0; j < 4; j++) acc[j] = make_float4(0.f, 0.f, 0.f, 0.f);

    const int s0 = c * CHUNK;
    const float* encb = enc + (size_t)b * S_ * ENC_;

    for (int r = w; r < CHUNK; r += 8) {
        const int s = s0 + r;
        const float4* er = (const float4*)(encb + (size_t)s * ENC_);

        float4 ev[4];
#pragma unroll
        for (int j = 0; j < 4; j++) ev[j] = __ldcs(&er[lane + 32 * j]);  // streaming, 4 indep loads

        float dot = 0.f;
#pragma unroll
        for (int j = 0; j < 4; j++) {
            dot += ev[j].x * subr[j].x + ev[j].y * subr[j].y +
                   ev[j].z * subr[j].z + ev[j].w * subr[j].w;
        }
#pragma unroll
        for (int o = 16; o > 0; o >>= 1) dot += __shfl_xor_sync(0xffffffffu, dot, o);

        if (lane == 0) g_logits[b * S_ + s] = dot;

        // online softmax update (warp-uniform)
        const float mn    = fmaxf(m, dot);
        const float scale = __expf(m - mn);
        const float p     = __expf(dot - mn);
        l = l * scale + p;
#pragma unroll
        for (int j = 0; j < 4; j++) {
            acc[j].x = acc[j].x * scale + p * ev[j].x;
            acc[j].y = acc[j].y * scale + p * ev[j].y;
            acc[j].z = acc[j].z * scale + p * ev[j].z;
            acc[j].w = acc[j].w * scale + p * ev[j].w;
        }
        m = mn;
    }

    // spill warp state to smem
    float4* arow = (float4*)accsm[w];
#pragma unroll
    for (int j = 0; j < 4; j++) arow[lane + 32 * j] = acc[j];
    if (lane == 0) { msm[w] = m; lsm[w] = l; }
    __syncthreads();

    // block merge (every thread redundantly computes M,L — cheap)
    float M = -1e30f;
#pragma unroll
    for (int ww = 0; ww < 8; ww++) M = fmaxf(M, msm[ww]);
    float L = 0.f;
    float wts[8];
#pragma unroll
    for (int ww = 0; ww < 8; ww++) {
        wts[ww] = __expf(msm[ww] - M);
        L += lsm[ww] * wts[ww];
    }

    const int cid = b * NCHUNK + c;
    if (tid == 0) { g_pm[cid] = M; g_pl[cid] = L; }

    for (int e = tid; e < ENC_; e += 256) {
        float a = 0.f;
#pragma unroll
        for (int ww = 0; ww < 8; ww++) a += accsm[ww][e] * wts[ww];
        g_pacc[(size_t)cid * ENC_ + e] = a;
    }
}

// ============================================================
// Kernel 3: finalize — merge chunk partials, write attn + sumResult
// grid = B_, block = 256
// d_out layout: attn [B,1,S] then sumResult [B,ENC]
// ============================================================
__global__ __launch_bounds__(256) void finalize(float* __restrict__ out) {
    const int b   = blockIdx.x;
    const int tid = threadIdx.x;

    // global max/denom across chunks (redundant per thread; 8 loads each)
    float M = -1e30f;
#pragma unroll
    for (int c = 0; c < NCHUNK; c++) M = fmaxf(M, g_pm[b * NCHUNK + c]);
    float L = 0.f;
    float wts[NCHUNK];
#pragma unroll
    for (int c = 0; c < NCHUNK; c++) {
        wts[c] = __expf(g_pm[b * NCHUNK + c] - M);
        L += g_pl[b * NCHUNK + c] * wts[c];
    }
    const float invL = 1.f / L;

    // attn probabilities from stored logits
    const float* lg = g_logits + b * S_;
    float* attn_out = out + (size_t)b * S_;
    for (int s = tid; s < S_; s += 256)
        attn_out[s] = __expf(lg[s] - M) * invL;

    // sumResult
    float* sum_out = out + (size_t)B_ * S_ + (size_t)b * ENC_;
    for (int e = tid; e < ENC_; e += 256) {
        float a = 0.f;
#pragma unroll
        for (int c = 0; c < NCHUNK; c++)
            a += g_pacc[(size_t)(b * NCHUNK + c) * ENC_ + e] * wts[c];
        sum_out[e] = a * invL;
    }
}

// ============================================================
extern "C" void kernel_launch(void* const* d_in, const int* in_sizes, int n_in,
                              void* d_out, int out_size) {
    const float* dec = (const float*)d_in[0];  // [64,1,512]
    const float* enc = (const float*)d_in[1];  // [64,4096,512]
    const float* W   = (const float*)d_in[2];  // [512,512]
    float* out = (float*)d_out;

    sub_kernel<<<dim3(ENC_ / 64, B_), 256>>>(dec, W);
    attn_pass1<<<dim3(NCHUNK, B_), 256>>>(enc);
    finalize<<<B_, 256>>>(out);
}